// round 16
// baseline (speedup 1.0000x reference)
#include <cuda_runtime.h>
#include <cuda_fp16.h>
#include <math.h>

#define N_NODES 50000
#define N_EDGES 600000

// UVh[node][0:128] = z@W1[0:128,:] + b1 ; UVh[node][128:256] = z@W1[128:256,:]
__device__ __half g_UVh[(size_t)N_NODES * 256];

__device__ __forceinline__ unsigned smem_u32(const void* p) {
    return (unsigned)__cvta_generic_to_shared(p);
}

// ---------------------------------------------------------------------------
// Kernel 1: tensor-core GEMM. UV = z @ Wcat (M=50000, K=128, N=256).
// One block = 64 M-rows; loops over 4 N-tiles of 64.
// B tile kept in natural [k][n] layout (direct vectorized fp32->fp16 convert
// from W1, no transpose) and fed to MMA via ldmatrix.trans.
// 256 threads = 8 warps in 2(m) x 4(n); warp tile 32m x 16n via m16n8k16.
// ---------------------------------------------------------------------------
__global__ __launch_bounds__(256) void uv_gemm_tc(
    const float* __restrict__ z, const float* __restrict__ W1,
    const float* __restrict__ b1)
{
    __shared__ __half Ah[64][136];   // [m][k], padded -> conflict-free ldmatrix
    __shared__ __half Bh[128][72];   // [k][n] (+8 pad -> 144B row stride)

    const int tid = threadIdx.x;
    const int m0 = blockIdx.x * 64;
    const int wid = tid >> 5, lane = tid & 31;
    const int warp_m = wid >> 2;     // 0..1
    const int warp_n = wid & 3;      // 0..3
    const int l15 = lane & 15;

    // --- A tile: 64 rows x 128 k, fp32 -> fp16, coalesced float4 ---
    #pragma unroll
    for (int i = tid; i < 64 * 32; i += 256) {
        int r = i >> 5, c4 = i & 31;
        float4 v = make_float4(0.f, 0.f, 0.f, 0.f);
        int gm = m0 + r;
        if (gm < N_NODES) v = *(const float4*)(z + (size_t)gm * 128 + c4 * 4);
        __half2* dst = (__half2*)&Ah[r][c4 * 4];
        dst[0] = __floats2half2_rn(v.x, v.y);
        dst[1] = __floats2half2_rn(v.z, v.w);
    }

    const int t_row = tid >> 4;      // 0..15 (k row group)
    const int t_c4  = tid & 15;      // 0..15 (float4 within 64-col row)

    #pragma unroll
    for (int bn = 0; bn < 4; bn++) {
        const bool hi = (bn >= 2);
        const int wbase = hi ? 128 : 0;
        const int jbase = bn * 64 - (hi ? 128 : 0);

        __syncthreads();   // Ah ready (bn=0) / prior Bh consumers done (bn>0)

        // --- B tile: Bh[k][n] = fp16(W1[wbase+k][jbase+n]), vectorized ---
        #pragma unroll
        for (int kk = 0; kk < 8; kk++) {
            int k = kk * 16 + t_row;
            float4 v = *(const float4*)(W1 + (size_t)(wbase + k) * 128 + jbase + t_c4 * 4);
            __half2* dst = (__half2*)&Bh[k][t_c4 * 4];
            dst[0] = __floats2half2_rn(v.x, v.y);
            dst[1] = __floats2half2_rn(v.z, v.w);
        }
        __syncthreads();

        float acc[2][2][4];
        #pragma unroll
        for (int tm = 0; tm < 2; tm++)
            #pragma unroll
            for (int tn = 0; tn < 2; tn++)
                #pragma unroll
                for (int i = 0; i < 4; i++) acc[tm][tn][i] = 0.f;

        #pragma unroll
        for (int kb = 0; kb < 8; kb++) {
            unsigned a[2][4], b[2][2];
            #pragma unroll
            for (int tm = 0; tm < 2; tm++) {
                int row = warp_m * 32 + tm * 16 + l15;
                int col = kb * 16 + (lane >> 4) * 8;
                unsigned addr = smem_u32(&Ah[row][col]);
                asm volatile("ldmatrix.sync.aligned.m8n8.x4.shared.b16 {%0,%1,%2,%3}, [%4];"
                    : "=r"(a[tm][0]), "=r"(a[tm][1]), "=r"(a[tm][2]), "=r"(a[tm][3])
                    : "r"(addr));
            }
            #pragma unroll
            for (int tn = 0; tn < 2; tn++) {
                // trans-ldmatrix from [k][n]: lanes 0..15 give rows k0..k0+15
                int krow = kb * 16 + l15;
                int ncol = warp_n * 16 + tn * 8;
                unsigned addr = smem_u32(&Bh[krow][ncol]);
                asm volatile("ldmatrix.sync.aligned.m8n8.x2.trans.shared.b16 {%0,%1}, [%2];"
                    : "=r"(b[tn][0]), "=r"(b[tn][1]) : "r"(addr));
            }
            #pragma unroll
            for (int tm = 0; tm < 2; tm++)
                #pragma unroll
                for (int tn = 0; tn < 2; tn++)
                    asm volatile("mma.sync.aligned.m16n8k16.row.col.f32.f16.f16.f32 "
                        "{%0,%1,%2,%3},{%4,%5,%6,%7},{%8,%9},{%0,%1,%2,%3};"
                        : "+f"(acc[tm][tn][0]), "+f"(acc[tm][tn][1]),
                          "+f"(acc[tm][tn][2]), "+f"(acc[tm][tn][3])
                        : "r"(a[tm][0]), "r"(a[tm][1]), "r"(a[tm][2]), "r"(a[tm][3]),
                          "r"(b[tn][0]), "r"(b[tn][1]));
        }

        // --- epilogue: fold b1 into U half, fp16 store ---
        #pragma unroll
        for (int tm = 0; tm < 2; tm++) {
            #pragma unroll
            for (int tn = 0; tn < 2; tn++) {
                int c = warp_n * 16 + tn * 8 + 2 * (lane & 3);   // within 64-col tile
                float bx = 0.f, by = 0.f;
                if (!hi) {
                    bx = b1[bn * 64 + c];
                    by = b1[bn * 64 + c + 1];
                }
                int r0 = m0 + warp_m * 32 + tm * 16 + (lane >> 2);
                int r1 = r0 + 8;
                if (r0 < N_NODES)
                    *(__half2*)(g_UVh + (size_t)r0 * 256 + bn * 64 + c) =
                        __floats2half2_rn(acc[tm][tn][0] + bx, acc[tm][tn][1] + by);
                if (r1 < N_NODES)
                    *(__half2*)(g_UVh + (size_t)r1 * 256 + bn * 64 + c) =
                        __floats2half2_rn(acc[tm][tn][2] + bx, acc[tm][tn][3] + by);
            }
        }
    }
}

// ---------------------------------------------------------------------------
// Kernel 2: edge epilogue. 8 lanes per edge, 4 edges per warp, half2 math.
//   h = relu(U'[e0] + V[e1]);  out = sigmoid(h . W2 + b2)
// Lane loads 32B from U and 32B from V (16 hidden units each).
// ---------------------------------------------------------------------------
__global__ __launch_bounds__(256) void edge_kernel(
    const int* __restrict__ e32,
    const float* __restrict__ W2, const float* __restrict__ b2,
    float* __restrict__ out)
{
    __shared__ int is64s;
    const int tid = threadIdx.x;
    if (tid == 0) {
        int any_hi = 0;
        #pragma unroll
        for (int i = 1; i < 64; i += 2) any_hi |= e32[i];
        is64s = (any_hi == 0);
    }
    __syncthreads();
    const int is64 = is64s;

    const int warp = tid >> 5, lane = tid & 31;
    const int g  = lane >> 3;        // 0..3: which edge of the quad
    const int sl = lane & 7;         // lane within edge group

    // W2 slice: 16 fp32 -> 8 half2 registers
    __half2 w2h[8];
    #pragma unroll
    for (int q = 0; q < 4; q++) {
        float4 w = *(const float4*)(W2 + sl * 16 + q * 4);
        w2h[q * 2]     = __floats2half2_rn(w.x, w.y);
        w2h[q * 2 + 1] = __floats2half2_rn(w.z, w.w);
    }
    const float bias2 = __ldg(b2);
    const long long* e64 = (const long long*)e32;

    const int gw = blockIdx.x * 8 + warp;
    const int stride = gridDim.x * 8 * 4;
    const __half2 z2 = __float2half2_rn(0.f);

    for (int e = gw * 4 + g; e < N_EDGES; e += stride) {
        int s, t;
        if (is64) {
            s = (int)e64[e];
            t = (int)e64[(size_t)N_EDGES + e];
        } else {
            s = e32[e];
            t = e32[(size_t)N_EDGES + e];
        }

        const uint4* up = (const uint4*)(g_UVh + (size_t)s * 256 + sl * 16);
        const uint4* vp = (const uint4*)(g_UVh + (size_t)t * 256 + 128 + sl * 16);
        uint4 ua = up[0], ub = up[1];
        uint4 va = vp[0], vb = vp[1];

        __half2 acc2;
        {
            __half2 h;
            h = __hmax2(__hadd2(*(__half2*)&ua.x, *(__half2*)&va.x), z2);
            acc2 = __hmul2(h, w2h[0]);
            h = __hmax2(__hadd2(*(__half2*)&ua.y, *(__half2*)&va.y), z2);
            acc2 = __hfma2(h, w2h[1], acc2);
            h = __hmax2(__hadd2(*(__half2*)&ua.z, *(__half2*)&va.z), z2);
            acc2 = __hfma2(h, w2h[2], acc2);
            h = __hmax2(__hadd2(*(__half2*)&ua.w, *(__half2*)&va.w), z2);
            acc2 = __hfma2(h, w2h[3], acc2);
            h = __hmax2(__hadd2(*(__half2*)&ub.x, *(__half2*)&vb.x), z2);
            acc2 = __hfma2(h, w2h[4], acc2);
            h = __hmax2(__hadd2(*(__half2*)&ub.y, *(__half2*)&vb.y), z2);
            acc2 = __hfma2(h, w2h[5], acc2);
            h = __hmax2(__hadd2(*(__half2*)&ub.z, *(__half2*)&vb.z), z2);
            acc2 = __hfma2(h, w2h[6], acc2);
            h = __hmax2(__hadd2(*(__half2*)&ub.w, *(__half2*)&vb.w), z2);
            acc2 = __hfma2(h, w2h[7], acc2);
        }
        float2 af = __half22float2(acc2);
        float acc = af.x + af.y;

        acc += __shfl_xor_sync(0xFFFFFFFFu, acc, 4);
        acc += __shfl_xor_sync(0xFFFFFFFFu, acc, 2);
        acc += __shfl_xor_sync(0xFFFFFFFFu, acc, 1);

        if (sl == 0) {
            float logit = acc + bias2;
            out[e] = 1.0f / (1.0f + expf(-logit));
        }
    }
}

// ---------------------------------------------------------------------------
extern "C" void kernel_launch(void* const* d_in, const int* in_sizes, int n_in,
                              void* d_out, int out_size)
{
    const float* z  = (const float*)d_in[0];
    const int*   e  = (const int*)d_in[1];
    const float* W1 = (const float*)d_in[2];
    const float* b1 = (const float*)d_in[3];
    const float* W2 = (const float*)d_in[4];
    const float* b2 = (const float*)d_in[5];
    float* out = (float*)d_out;

    uv_gemm_tc<<<(N_NODES + 63) / 64, 256>>>(z, W1, b1);
    edge_kernel<<<1184, 256>>>(e, W2, b2, out);
}

// round 17
// speedup vs baseline: 1.2098x; 1.2098x over previous
#include <cuda_runtime.h>
#include <cuda_fp16.h>
#include <math.h>

#define N_NODES 50000
#define N_EDGES 600000

// UVh[node][0:128] = z@W1[0:128,:] + b1 ; UVh[node][128:256] = z@W1[128:256,:]
__device__ __half g_UVh[(size_t)N_NODES * 256];

__device__ __forceinline__ unsigned smem_u32(const void* p) {
    return (unsigned)__cvta_generic_to_shared(p);
}

// ---------------------------------------------------------------------------
// Kernel 1: tensor-core GEMM (unchanged from R16). UV = z @ Wcat.
// ---------------------------------------------------------------------------
__global__ __launch_bounds__(256) void uv_gemm_tc(
    const float* __restrict__ z, const float* __restrict__ W1,
    const float* __restrict__ b1)
{
    __shared__ __half Ah[64][136];   // [m][k]
    __shared__ __half Bh[128][72];   // [k][n] (+8 pad)

    const int tid = threadIdx.x;
    const int m0 = blockIdx.x * 64;
    const int wid = tid >> 5, lane = tid & 31;
    const int warp_m = wid >> 2;
    const int warp_n = wid & 3;
    const int l15 = lane & 15;

    #pragma unroll
    for (int i = tid; i < 64 * 32; i += 256) {
        int r = i >> 5, c4 = i & 31;
        float4 v = make_float4(0.f, 0.f, 0.f, 0.f);
        int gm = m0 + r;
        if (gm < N_NODES) v = *(const float4*)(z + (size_t)gm * 128 + c4 * 4);
        __half2* dst = (__half2*)&Ah[r][c4 * 4];
        dst[0] = __floats2half2_rn(v.x, v.y);
        dst[1] = __floats2half2_rn(v.z, v.w);
    }

    const int t_row = tid >> 4;
    const int t_c4  = tid & 15;

    #pragma unroll
    for (int bn = 0; bn < 4; bn++) {
        const bool hi = (bn >= 2);
        const int wbase = hi ? 128 : 0;
        const int jbase = bn * 64 - (hi ? 128 : 0);

        __syncthreads();

        #pragma unroll
        for (int kk = 0; kk < 8; kk++) {
            int k = kk * 16 + t_row;
            float4 v = *(const float4*)(W1 + (size_t)(wbase + k) * 128 + jbase + t_c4 * 4);
            __half2* dst = (__half2*)&Bh[k][t_c4 * 4];
            dst[0] = __floats2half2_rn(v.x, v.y);
            dst[1] = __floats2half2_rn(v.z, v.w);
        }
        __syncthreads();

        float acc[2][2][4];
        #pragma unroll
        for (int tm = 0; tm < 2; tm++)
            #pragma unroll
            for (int tn = 0; tn < 2; tn++)
                #pragma unroll
                for (int i = 0; i < 4; i++) acc[tm][tn][i] = 0.f;

        #pragma unroll
        for (int kb = 0; kb < 8; kb++) {
            unsigned a[2][4], b[2][2];
            #pragma unroll
            for (int tm = 0; tm < 2; tm++) {
                int row = warp_m * 32 + tm * 16 + l15;
                int col = kb * 16 + (lane >> 4) * 8;
                unsigned addr = smem_u32(&Ah[row][col]);
                asm volatile("ldmatrix.sync.aligned.m8n8.x4.shared.b16 {%0,%1,%2,%3}, [%4];"
                    : "=r"(a[tm][0]), "=r"(a[tm][1]), "=r"(a[tm][2]), "=r"(a[tm][3])
                    : "r"(addr));
            }
            #pragma unroll
            for (int tn = 0; tn < 2; tn++) {
                int krow = kb * 16 + l15;
                int ncol = warp_n * 16 + tn * 8;
                unsigned addr = smem_u32(&Bh[krow][ncol]);
                asm volatile("ldmatrix.sync.aligned.m8n8.x2.trans.shared.b16 {%0,%1}, [%2];"
                    : "=r"(b[tn][0]), "=r"(b[tn][1]) : "r"(addr));
            }
            #pragma unroll
            for (int tm = 0; tm < 2; tm++)
                #pragma unroll
                for (int tn = 0; tn < 2; tn++)
                    asm volatile("mma.sync.aligned.m16n8k16.row.col.f32.f16.f16.f32 "
                        "{%0,%1,%2,%3},{%4,%5,%6,%7},{%8,%9},{%0,%1,%2,%3};"
                        : "+f"(acc[tm][tn][0]), "+f"(acc[tm][tn][1]),
                          "+f"(acc[tm][tn][2]), "+f"(acc[tm][tn][3])
                        : "r"(a[tm][0]), "r"(a[tm][1]), "r"(a[tm][2]), "r"(a[tm][3]),
                          "r"(b[tn][0]), "r"(b[tn][1]));
        }

        #pragma unroll
        for (int tm = 0; tm < 2; tm++) {
            #pragma unroll
            for (int tn = 0; tn < 2; tn++) {
                int c = warp_n * 16 + tn * 8 + 2 * (lane & 3);
                float bx = 0.f, by = 0.f;
                if (!hi) {
                    bx = b1[bn * 64 + c];
                    by = b1[bn * 64 + c + 1];
                }
                int r0 = m0 + warp_m * 32 + tm * 16 + (lane >> 2);
                int r1 = r0 + 8;
                if (r0 < N_NODES)
                    *(__half2*)(g_UVh + (size_t)r0 * 256 + bn * 64 + c) =
                        __floats2half2_rn(acc[tm][tn][0] + bx, acc[tm][tn][1] + by);
                if (r1 < N_NODES)
                    *(__half2*)(g_UVh + (size_t)r1 * 256 + bn * 64 + c) =
                        __floats2half2_rn(acc[tm][tn][2] + bx, acc[tm][tn][3] + by);
            }
        }
    }
}

// ---------------------------------------------------------------------------
// Kernel 2: edge epilogue. 8 lanes/edge, 8 edges/warp/iter (unroll-2),
// sector-exact gathers, next-iteration index prefetch, guarded stores only.
// Lane sl of a group loads rowU[sl] (bytes sl*16) and rowU[sl+8] (128+sl*16):
// every 32B sector fully covered exactly once.
// ---------------------------------------------------------------------------
__device__ __forceinline__ float edge_dot(
    const uint4& ua, const uint4& ub, const uint4& va, const uint4& vb,
    const __half2* w2h, __half2 z2)
{
    __half2 h, acc2;
    h = __hmax2(__hadd2(*(__half2*)&ua.x, *(__half2*)&va.x), z2);
    acc2 = __hmul2(h, w2h[0]);
    h = __hmax2(__hadd2(*(__half2*)&ua.y, *(__half2*)&va.y), z2);
    acc2 = __hfma2(h, w2h[1], acc2);
    h = __hmax2(__hadd2(*(__half2*)&ua.z, *(__half2*)&va.z), z2);
    acc2 = __hfma2(h, w2h[2], acc2);
    h = __hmax2(__hadd2(*(__half2*)&ua.w, *(__half2*)&va.w), z2);
    acc2 = __hfma2(h, w2h[3], acc2);
    h = __hmax2(__hadd2(*(__half2*)&ub.x, *(__half2*)&vb.x), z2);
    acc2 = __hfma2(h, w2h[4], acc2);
    h = __hmax2(__hadd2(*(__half2*)&ub.y, *(__half2*)&vb.y), z2);
    acc2 = __hfma2(h, w2h[5], acc2);
    h = __hmax2(__hadd2(*(__half2*)&ub.z, *(__half2*)&vb.z), z2);
    acc2 = __hfma2(h, w2h[6], acc2);
    h = __hmax2(__hadd2(*(__half2*)&ub.w, *(__half2*)&vb.w), z2);
    acc2 = __hfma2(h, w2h[7], acc2);
    float2 af = __half22float2(acc2);
    return af.x + af.y;
}

__global__ __launch_bounds__(256) void edge_kernel(
    const int* __restrict__ e32,
    const float* __restrict__ W2, const float* __restrict__ b2,
    float* __restrict__ out)
{
    __shared__ int is64s;
    const int tid = threadIdx.x;
    if (tid == 0) {
        int any_hi = 0;
        #pragma unroll
        for (int i = 1; i < 64; i += 2) any_hi |= e32[i];
        is64s = (any_hi == 0);
    }
    __syncthreads();
    const int is64 = is64s;
    const long long* e64 = (const long long*)e32;

    const int warp = tid >> 5, lane = tid & 31;
    const int g  = lane >> 3;        // group 0..3
    const int sl = lane & 7;

    // W2 slice matching sector-exact layout:
    // low chunk  = hidden [sl*8, sl*8+8)     (from rowU[sl])
    // high chunk = hidden [64+sl*8, +8)      (from rowU[sl+8])
    __half2 w2h[8];
    {
        float4 a0 = *(const float4*)(W2 + sl * 8);
        float4 a1 = *(const float4*)(W2 + sl * 8 + 4);
        float4 b0 = *(const float4*)(W2 + 64 + sl * 8);
        float4 b1v = *(const float4*)(W2 + 64 + sl * 8 + 4);
        w2h[0] = __floats2half2_rn(a0.x, a0.y);
        w2h[1] = __floats2half2_rn(a0.z, a0.w);
        w2h[2] = __floats2half2_rn(a1.x, a1.y);
        w2h[3] = __floats2half2_rn(a1.z, a1.w);
        w2h[4] = __floats2half2_rn(b0.x, b0.y);
        w2h[5] = __floats2half2_rn(b0.z, b0.w);
        w2h[6] = __floats2half2_rn(b1v.x, b1v.y);
        w2h[7] = __floats2half2_rn(b1v.z, b1v.w);
    }
    const float bias2 = __ldg(b2);
    const __half2 z2 = __float2half2_rn(0.f);

    const int w = blockIdx.x * 8 + warp;
    const int stride = gridDim.x * 8 * 8;       // edges consumed per chip-iter

    #define LOAD_IDX(e, s, t)                                   \
        do {                                                    \
            s = 0; t = 0;                                       \
            if ((e) < N_EDGES) {                                \
                if (is64) { s = (int)e64[e];                    \
                            t = (int)e64[(size_t)N_EDGES + (e)]; } \
                else      { s = e32[e];                         \
                            t = e32[(size_t)N_EDGES + (e)]; }   \
            }                                                   \
        } while (0)

    int eA = w * 8 + g;
    int eB = eA + 4;
    int sA, tA, sB, tB;
    LOAD_IDX(eA, sA, tA);
    LOAD_IDX(eB, sB, tB);

    while (eA < N_EDGES) {
        // --- issue all 8 gathers (sector-exact) ---
        const uint4* rUA = (const uint4*)(g_UVh + (size_t)sA * 256);
        const uint4* rVA = (const uint4*)(g_UVh + (size_t)tA * 256 + 128);
        const uint4* rUB = (const uint4*)(g_UVh + (size_t)sB * 256);
        const uint4* rVB = (const uint4*)(g_UVh + (size_t)tB * 256 + 128);
        uint4 uaA = rUA[sl], ubA = rUA[sl + 8];
        uint4 vaA = rVA[sl], vbA = rVA[sl + 8];
        uint4 uaB = rUB[sl], ubB = rUB[sl + 8];
        uint4 vaB = rVB[sl], vbB = rVB[sl + 8];

        // --- prefetch next iteration's indices under gather latency ---
        int enA = eA + stride, enB = eB + stride;
        int sA2, tA2, sB2, tB2;
        LOAD_IDX(enA, sA2, tA2);
        LOAD_IDX(enB, sB2, tB2);

        // --- compute + reduce + store (unconditional math, guarded store) ---
        float accA = edge_dot(uaA, ubA, vaA, vbA, w2h, z2);
        float accB = edge_dot(uaB, ubB, vaB, vbB, w2h, z2);

        accA += __shfl_xor_sync(0xFFFFFFFFu, accA, 4);
        accB += __shfl_xor_sync(0xFFFFFFFFu, accB, 4);
        accA += __shfl_xor_sync(0xFFFFFFFFu, accA, 2);
        accB += __shfl_xor_sync(0xFFFFFFFFu, accB, 2);
        accA += __shfl_xor_sync(0xFFFFFFFFu, accA, 1);
        accB += __shfl_xor_sync(0xFFFFFFFFu, accB, 1);

        if (sl == 0) {
            out[eA] = 1.0f / (1.0f + __expf(-(accA + bias2)));
            if (eB < N_EDGES)
                out[eB] = 1.0f / (1.0f + __expf(-(accB + bias2)));
        }

        eA = enA; eB = enB;
        sA = sA2; tA = tA2; sB = sB2; tB = tB2;
    }
    #undef LOAD_IDX
}

// ---------------------------------------------------------------------------
extern "C" void kernel_launch(void* const* d_in, const int* in_sizes, int n_in,
                              void* d_out, int out_size)
{
    const float* z  = (const float*)d_in[0];
    const int*   e  = (const int*)d_in[1];
    const float* W1 = (const float*)d_in[2];
    const float* b1 = (const float*)d_in[3];
    const float* W2 = (const float*)d_in[4];
    const float* b2 = (const float*)d_in[5];
    float* out = (float*)d_out;

    uv_gemm_tc<<<(N_NODES + 63) / 64, 256>>>(z, W1, b1);
    edge_kernel<<<1184, 256>>>(e, W2, b2, out);
}